// round 3
// baseline (speedup 1.0000x reference)
#include <cuda_runtime.h>
#include <mma.h>
#include <cstdint>

using namespace nvcuda;

// Problem constants
#define B_  2
#define N_  1024
#define DIM_ 1024
#define H_  16
#define DH_ 64

// ---------------- scratch buffers (device globals; no allocation) -------------
__device__ float g_xn[B_ * N_ * DIM_];          // LN(x)
__device__ float g_q [B_ * H_ * N_ * DH_];      // q in [b,h,i,d]
__device__ float g_k [B_ * N_ * DH_];           // k body [b,j,d]
__device__ float g_v [B_ * N_ * DH_];           // v body [b,j,d]
__device__ float g_nk[DH_];                     // l2norm(null_k)*4
__device__ float g_nv[DH_];                     // null_v
__device__ float g_o [B_ * N_ * DIM_];          // attention out, [b,i, h*64+d]
__device__ float g_y [B_ * N_ * DIM_];          // out-proj result

// ---------------- LayerNorm: one block per row of 1024 -----------------------
__global__ __launch_bounds__(256) void ln_kernel(const float* __restrict__ x,
                                                 const float* __restrict__ g,
                                                 float* __restrict__ out) {
    const int row = blockIdx.x;
    const int tid = threadIdx.x;
    float4 a = ((const float4*)(x + (size_t)row * 1024))[tid];
    float s = a.x + a.y + a.z + a.w;
    float q = a.x * a.x + a.y * a.y + a.z * a.z + a.w * a.w;
    #pragma unroll
    for (int o = 16; o > 0; o >>= 1) {
        s += __shfl_xor_sync(0xffffffffu, s, o);
        q += __shfl_xor_sync(0xffffffffu, q, o);
    }
    __shared__ float ss[8], qq[8];
    if ((tid & 31) == 0) { ss[tid >> 5] = s; qq[tid >> 5] = q; }
    __syncthreads();
    if (tid < 32) {
        float s2 = (tid < 8) ? ss[tid] : 0.f;
        float q2 = (tid < 8) ? qq[tid] : 0.f;
        #pragma unroll
        for (int o = 4; o > 0; o >>= 1) {
            s2 += __shfl_xor_sync(0xffffffffu, s2, o);
            q2 += __shfl_xor_sync(0xffffffffu, q2, o);
        }
        if (tid == 0) { ss[0] = s2; qq[0] = q2; }
    }
    __syncthreads();
    const float mean = ss[0] * (1.f / 1024.f);
    const float var  = qq[0] * (1.f / 1024.f) - mean * mean;
    const float rstd = rsqrtf(var + 1e-5f);
    float4 gv = ((const float4*)g)[tid];
    float4 o4;
    o4.x = (a.x - mean) * rstd * gv.x;
    o4.y = (a.y - mean) * rstd * gv.y;
    o4.z = (a.z - mean) * rstd * gv.z;
    o4.w = (a.w - mean) * rstd * gv.w;
    ((float4*)(out + (size_t)row * 1024))[tid] = o4;
}

// ---------------- tf32 WMMA GEMM ----------------------------------------------
#define GEMM_BM 128
#define GEMM_BN 64
#define GEMM_BK 32
#define GEMM_LDA 36
#define GEMM_LDB 36

// Fused QKV GEMM: A = g_xn (2048x1024), cols 0..1023 -> q, 1024..1087 -> k, 1088..1151 -> v
__global__ __launch_bounds__(256) void gemm_qkv_kernel(const float* __restrict__ Wq,
                                                       const float* __restrict__ Wkv) {
    __shared__ float As[GEMM_BM * GEMM_LDA];
    __shared__ float Bs[GEMM_BN * GEMM_LDB];
    const int nbase = blockIdx.x * GEMM_BN;      // 0..1151 step 64
    const int m0    = blockIdx.y * GEMM_BM;      // 0..1920 step 128
    const float* __restrict__ A = g_xn;
    const float* Bp = (nbase < 1024) ? (Wq + (size_t)nbase * 1024)
                                     : (Wkv + (size_t)(nbase - 1024) * 1024);
    const int tid = threadIdx.x;
    const int warp = tid >> 5;
    const int wr = warp >> 1, wc = warp & 1;

    wmma::fragment<wmma::accumulator, 16, 16, 8, float> c[2][2];
    #pragma unroll
    for (int i = 0; i < 2; i++)
        #pragma unroll
        for (int j = 0; j < 2; j++) wmma::fill_fragment(c[i][j], 0.f);

    const int af = tid & 7, ar = tid >> 3;   // A: 8 float4-cols, 32 row-groups

    for (int k0 = 0; k0 < 1024; k0 += GEMM_BK) {
        #pragma unroll
        for (int i = 0; i < 4; i++) {
            int r = ar + 32 * i;
            *(float4*)(As + r * GEMM_LDA + af * 4) =
                *(const float4*)(A + (size_t)(m0 + r) * 1024 + k0 + af * 4);
        }
        #pragma unroll
        for (int i = 0; i < 2; i++) {
            int r = ar + 32 * i;
            *(float4*)(Bs + r * GEMM_LDB + af * 4) =
                *(const float4*)(Bp + (size_t)r * 1024 + k0 + af * 4);
        }
        __syncthreads();
        #pragma unroll
        for (int kk = 0; kk < 4; kk++) {
            wmma::fragment<wmma::matrix_a, 16, 16, 8, wmma::precision::tf32, wmma::row_major> a[2];
            wmma::fragment<wmma::matrix_b, 16, 16, 8, wmma::precision::tf32, wmma::col_major> b[2];
            #pragma unroll
            for (int i = 0; i < 2; i++) {
                wmma::load_matrix_sync(a[i], As + (wr * 32 + i * 16) * GEMM_LDA + kk * 8, GEMM_LDA);
                #pragma unroll
                for (int t = 0; t < a[i].num_elements; t++)
                    a[i].x[t] = wmma::__float_to_tf32(a[i].x[t]);
            }
            #pragma unroll
            for (int j = 0; j < 2; j++) {
                wmma::load_matrix_sync(b[j], Bs + (wc * 32 + j * 16) * GEMM_LDB + kk * 8, GEMM_LDB);
                #pragma unroll
                for (int t = 0; t < b[j].num_elements; t++)
                    b[j].x[t] = wmma::__float_to_tf32(b[j].x[t]);
            }
            #pragma unroll
            for (int i = 0; i < 2; i++)
                #pragma unroll
                for (int j = 0; j < 2; j++)
                    wmma::mma_sync(c[i][j], a[i], b[j], c[i][j]);
        }
        __syncthreads();
    }

    // epilogue: scatter into q [b,h,i,d] / k,v [b,j,d] (all contiguous ld=64 tiles)
    const int b  = m0 >> 10;
    const int i0 = m0 & 1023;
    float* dest;
    if (nbase < 1024) {
        const int h = nbase >> 6;
        dest = g_q + ((size_t)(b * 16 + h) * 1024 + i0) * 64;
    } else if (nbase == 1024) {
        dest = g_k + ((size_t)b * 1024 + i0) * 64;
    } else {
        dest = g_v + ((size_t)b * 1024 + i0) * 64;
    }
    #pragma unroll
    for (int i = 0; i < 2; i++)
        #pragma unroll
        for (int j = 0; j < 2; j++)
            wmma::store_matrix_sync(dest + (size_t)(wr * 32 + i * 16) * 64 + (wc * 32 + j * 16),
                                    c[i][j], 64, wmma::mem_row_major);
}

// Out-projection GEMM: g_y = g_o @ w_out^T
__global__ __launch_bounds__(256) void gemm_out_kernel(const float* __restrict__ Wout) {
    __shared__ float As[GEMM_BM * GEMM_LDA];
    __shared__ float Bs[GEMM_BN * GEMM_LDB];
    const int nbase = blockIdx.x * GEMM_BN;
    const int m0    = blockIdx.y * GEMM_BM;
    const float* __restrict__ A = g_o;
    const float* Bp = Wout + (size_t)nbase * 1024;
    const int tid = threadIdx.x;
    const int warp = tid >> 5;
    const int wr = warp >> 1, wc = warp & 1;

    wmma::fragment<wmma::accumulator, 16, 16, 8, float> c[2][2];
    #pragma unroll
    for (int i = 0; i < 2; i++)
        #pragma unroll
        for (int j = 0; j < 2; j++) wmma::fill_fragment(c[i][j], 0.f);

    const int af = tid & 7, ar = tid >> 3;

    for (int k0 = 0; k0 < 1024; k0 += GEMM_BK) {
        #pragma unroll
        for (int i = 0; i < 4; i++) {
            int r = ar + 32 * i;
            *(float4*)(As + r * GEMM_LDA + af * 4) =
                *(const float4*)(A + (size_t)(m0 + r) * 1024 + k0 + af * 4);
        }
        #pragma unroll
        for (int i = 0; i < 2; i++) {
            int r = ar + 32 * i;
            *(float4*)(Bs + r * GEMM_LDB + af * 4) =
                *(const float4*)(Bp + (size_t)r * 1024 + k0 + af * 4);
        }
        __syncthreads();
        #pragma unroll
        for (int kk = 0; kk < 4; kk++) {
            wmma::fragment<wmma::matrix_a, 16, 16, 8, wmma::precision::tf32, wmma::row_major> a[2];
            wmma::fragment<wmma::matrix_b, 16, 16, 8, wmma::precision::tf32, wmma::col_major> b[2];
            #pragma unroll
            for (int i = 0; i < 2; i++) {
                wmma::load_matrix_sync(a[i], As + (wr * 32 + i * 16) * GEMM_LDA + kk * 8, GEMM_LDA);
                #pragma unroll
                for (int t = 0; t < a[i].num_elements; t++)
                    a[i].x[t] = wmma::__float_to_tf32(a[i].x[t]);
            }
            #pragma unroll
            for (int j = 0; j < 2; j++) {
                wmma::load_matrix_sync(b[j], Bs + (wc * 32 + j * 16) * GEMM_LDB + kk * 8, GEMM_LDB);
                #pragma unroll
                for (int t = 0; t < b[j].num_elements; t++)
                    b[j].x[t] = wmma::__float_to_tf32(b[j].x[t]);
            }
            #pragma unroll
            for (int i = 0; i < 2; i++)
                #pragma unroll
                for (int j = 0; j < 2; j++)
                    wmma::mma_sync(c[i][j], a[i], b[j], c[i][j]);
        }
        __syncthreads();
    }
    #pragma unroll
    for (int i = 0; i < 2; i++)
        #pragma unroll
        for (int j = 0; j < 2; j++)
            wmma::store_matrix_sync(g_y + (size_t)(m0 + wr * 32 + i * 16) * 1024 + nbase + wc * 32 + j * 16,
                                    c[i][j], 1024, wmma::mem_row_major);
}

// ---------------- l2norm (warp per 64-wide row) -------------------------------
// rows [0, 32768): g_q rows; [32768, 34816): g_k rows; 34816: null_k; 34817: null_v
__global__ __launch_bounds__(256) void l2norm_kernel(const float* __restrict__ null_kv) {
    const int row  = blockIdx.x * 8 + (threadIdx.x >> 5);
    const int lane = threadIdx.x & 31;
    if (row > 34817) return;
    if (row == 34816) {
        float v0 = null_kv[lane], v1 = null_kv[lane + 32];
        float s = v0 * v0 + v1 * v1;
        #pragma unroll
        for (int o = 16; o > 0; o >>= 1) s += __shfl_xor_sync(0xffffffffu, s, o);
        float sc = 4.f / fmaxf(sqrtf(s), 1e-12f);
        g_nk[lane] = v0 * sc; g_nk[lane + 32] = v1 * sc;
        return;
    }
    if (row == 34817) {
        g_nv[lane] = null_kv[64 + lane];
        g_nv[lane + 32] = null_kv[96 + lane];
        return;
    }
    float* p = (row < 32768) ? (g_q + (size_t)row * 64)
                             : (g_k + (size_t)(row - 32768) * 64);
    float v0 = p[lane], v1 = p[lane + 32];
    float s = v0 * v0 + v1 * v1;
    #pragma unroll
    for (int o = 16; o > 0; o >>= 1) s += __shfl_xor_sync(0xffffffffu, s, o);
    float sc = 4.f / fmaxf(sqrtf(s), 1e-12f);
    p[lane] = v0 * sc; p[lane + 32] = v1 * sc;
}

// ---------------- attention ---------------------------------------------------
// grid = (16 q-tiles, 32 bh). 64-query tile, loop over 16 key tiles of 64.
// Single-pass softmax (no max subtraction; scores bounded: |q.k| <= 16, bias ~0.1).
#define LDP 68
__global__ __launch_bounds__(256) void attn_kernel(const float* __restrict__ bias) {
    extern __shared__ float sm[];
    float* Qs   = sm;                 // 64*68
    float* Ks   = sm + 1 * 64 * LDP;  // 64*68
    float* Vs   = sm + 2 * 64 * LDP;  // 64*68
    float* Bs   = sm + 3 * 64 * LDP;  // 64*68  bias tile (coalesced staging)
    float* Ss   = sm + 4 * 64 * LDP;  // 64*68  S -> P -> final O
    float* e0   = sm + 5 * 64 * LDP;  // 64
    float* den  = e0 + 64;            // 64
    float* denp = den + 64;           // 256

    const int qt = blockIdx.x;
    const int bh = blockIdx.y;
    const int b  = bh >> 4;
    const int h  = bh & 15;
    const int i0 = qt * 64;
    const int tid = threadIdx.x;
    const int warp = tid >> 5;
    const int wr = warp >> 1, wc = warp & 1;

    const float* bias_p = bias + (size_t)bh * 1024 * 1025;
    const float* kbase  = g_k + (size_t)b * 1024 * 64;
    const float* vbase  = g_v + (size_t)b * 1024 * 64;

    // load Q tile (contiguous 64x64)
    {
        const float* qp = g_q + ((size_t)(b * 16 + h) * 1024 + i0) * 64;
        for (int i = tid; i < 64 * 16; i += 256) {
            int r = i >> 4, c4 = i & 15;
            *(float4*)(Qs + r * LDP + c4 * 4) = *(const float4*)(qp + r * 64 + c4 * 4);
        }
    }
    __syncthreads();

    // null-key column: e0[r] = exp(q_r . nk + bias[.., 0]); den init
    if (tid < 64) {
        float s = 0.f;
        #pragma unroll 8
        for (int d = 0; d < 64; d++) s += Qs[tid * LDP + d] * g_nk[d];
        float e = __expf(s + bias_p[(size_t)(i0 + tid) * 1025]);
        e0[tid] = e;
        den[tid] = e;
    }

    wmma::fragment<wmma::accumulator, 16, 16, 8, float> of[2];
    wmma::fill_fragment(of[0], 0.f);
    wmma::fill_fragment(of[1], 0.f);

    for (int kt = 0; kt < 16; kt++) {
        const int j0 = kt * 64;
        __syncthreads();  // protect Ks/Vs/Bs from previous iteration's readers
        // load K, V tiles (float4, coalesced)
        for (int i = tid; i < 64 * 16; i += 256) {
            int r = i >> 4, c4 = i & 15;
            *(float4*)(Ks + r * LDP + c4 * 4) =
                *(const float4*)(kbase + (size_t)(j0 + r) * 64 + c4 * 4);
            *(float4*)(Vs + r * LDP + c4 * 4) =
                *(const float4*)(vbase + (size_t)(j0 + r) * 64 + c4 * 4);
        }
        // load bias tile, fully coalesced: consecutive tid -> consecutive j
        // (rows have odd stride 1025 so float4 is impossible; 32 consecutive
        //  scalar lanes = one 128B transaction per warp instr)
        for (int idx = tid; idx < 64 * 64; idx += 256) {
            int r = idx >> 6, c = idx & 63;
            Bs[r * LDP + c] = bias_p[(size_t)(i0 + r) * 1025 + 1 + j0 + c];
        }
        __syncthreads();

        // S = Q K^T
        wmma::fragment<wmma::accumulator, 16, 16, 8, float> sf[2];
        wmma::fill_fragment(sf[0], 0.f);
        wmma::fill_fragment(sf[1], 0.f);
        #pragma unroll
        for (int kk = 0; kk < 8; kk++) {
            wmma::fragment<wmma::matrix_a, 16, 16, 8, wmma::precision::tf32, wmma::row_major> a;
            wmma::load_matrix_sync(a, Qs + (wr * 16) * LDP + kk * 8, LDP);
            #pragma unroll
            for (int t = 0; t < a.num_elements; t++) a.x[t] = wmma::__float_to_tf32(a.x[t]);
            #pragma unroll
            for (int j = 0; j < 2; j++) {
                wmma::fragment<wmma::matrix_b, 16, 16, 8, wmma::precision::tf32, wmma::col_major> bfr;
                wmma::load_matrix_sync(bfr, Ks + (wc * 32 + j * 16) * LDP + kk * 8, LDP);
                #pragma unroll
                for (int t = 0; t < bfr.num_elements; t++) bfr.x[t] = wmma::__float_to_tf32(bfr.x[t]);
                wmma::mma_sync(sf[j], a, bfr, sf[j]);
            }
        }
        #pragma unroll
        for (int j = 0; j < 2; j++)
            wmma::store_matrix_sync(Ss + (wr * 16) * LDP + wc * 32 + j * 16, sf[j], LDP,
                                    wmma::mem_row_major);
        __syncthreads();

        // P = exp(S + bias); partial row-sums (deterministic, no atomics)
        {
            const int r = tid >> 2, cb = (tid & 3) * 16;
            float local = 0.f;
            #pragma unroll
            for (int c = 0; c < 16; c++) {
                float pv = __expf(Ss[r * LDP + cb + c] + Bs[r * LDP + cb + c]);
                Ss[r * LDP + cb + c] = pv;
                local += pv;
            }
            denp[tid] = local;
        }
        __syncthreads();
        if (tid < 64)
            den[tid] += denp[4 * tid] + denp[4 * tid + 1] + denp[4 * tid + 2] + denp[4 * tid + 3];

        // O += P V
        #pragma unroll
        for (int kk = 0; kk < 8; kk++) {
            wmma::fragment<wmma::matrix_a, 16, 16, 8, wmma::precision::tf32, wmma::row_major> a;
            wmma::load_matrix_sync(a, Ss + (wr * 16) * LDP + kk * 8, LDP);
            #pragma unroll
            for (int t = 0; t < a.num_elements; t++) a.x[t] = wmma::__float_to_tf32(a.x[t]);
            #pragma unroll
            for (int j = 0; j < 2; j++) {
                wmma::fragment<wmma::matrix_b, 16, 16, 8, wmma::precision::tf32, wmma::row_major> bfr;
                wmma::load_matrix_sync(bfr, Vs + (kk * 8) * LDP + wc * 32 + j * 16, LDP);
                #pragma unroll
                for (int t = 0; t < bfr.num_elements; t++) bfr.x[t] = wmma::__float_to_tf32(bfr.x[t]);
                wmma::mma_sync(of[j], a, bfr, of[j]);
            }
        }
    }
    __syncthreads();
    #pragma unroll
    for (int j = 0; j < 2; j++)
        wmma::store_matrix_sync(Ss + (wr * 16) * LDP + wc * 32 + j * 16, of[j], LDP,
                                wmma::mem_row_major);
    __syncthreads();

    // out = (O + e0 * nv) / den, written to [b, i, h*64+d]
    {
        const int r = tid >> 2, cb = (tid & 3) * 16;
        const float invd = 1.f / den[r];
        const float e = e0[r];
        float* op = g_o + ((size_t)(b * 1024 + i0 + r)) * 1024 + h * 64 + cb;
        #pragma unroll
        for (int c = 0; c < 16; c++)
            op[c] = (Ss[r * LDP + cb + c] + e * g_nv[cb + c]) * invd;
    }
}

// ---------------- launch -------------------------------------------------------
extern "C" void kernel_launch(void* const* d_in, const int* in_sizes, int n_in,
                              void* d_out, int out_size) {
    const float* x       = (const float*)d_in[0];
    const float* bias    = (const float*)d_in[1];
    const float* g_in    = (const float*)d_in[2];
    const float* w_q     = (const float*)d_in[3];
    const float* w_kv    = (const float*)d_in[4];
    const float* null_kv = (const float*)d_in[5];
    const float* w_out   = (const float*)d_in[6];
    const float* g_out   = (const float*)d_in[7];
    float* out = (float*)d_out;

    float* xn_p; cudaGetSymbolAddress((void**)&xn_p, g_xn);
    float* y_p;  cudaGetSymbolAddress((void**)&y_p,  g_y);

    const int ATTN_SMEM = (5 * 64 * LDP + 64 + 64 + 256) * 4;  // 88576 B
    cudaFuncSetAttribute(attn_kernel, cudaFuncAttributeMaxDynamicSharedMemorySize, ATTN_SMEM);

    // 1. LN(x) -> xn
    ln_kernel<<<2048, 256>>>(x, g_in, xn_p);
    // 2. fused QKV GEMM
    gemm_qkv_kernel<<<dim3(18, 16), 256>>>(w_q, w_kv);
    // 3. l2norm q rows, k rows; prep null k/v
    l2norm_kernel<<<(32768 + 2048 + 2 + 7) / 8, 256>>>(null_kv);
    // 4. attention
    attn_kernel<<<dim3(16, 32), 256, ATTN_SMEM>>>(bias);
    // 5. out projection
    gemm_out_kernel<<<dim3(16, 16), 256>>>(w_out);
    // 6. final LN -> d_out
    ln_kernel<<<2048, 256>>>(y_p, g_out, out);
}

// round 6
// speedup vs baseline: 1.4175x; 1.4175x over previous
#include <cuda_runtime.h>
#include <cuda_bf16.h>
#include <mma.h>
#include <cstdint>

using namespace nvcuda;
typedef __nv_bfloat16 bf16;

#define B_  2
#define N_  1024
#define DIM_ 1024
#define H_  16
#define DH_ 64

// ---------------- scratch (device globals; no allocation) ---------------------
__device__ float g_xn [2*1024*1024];
__device__ bf16  g_xnh[2*1024*1024], g_xnl[2*1024*1024];
__device__ bf16  g_wh [1152*1024],   g_wl [1152*1024];     // combined wq+wkv split
__device__ bf16  g_woh[1024*1024],   g_wol[1024*1024];
__device__ float g_q  [2*16*1024*64];
__device__ float g_k  [2*1024*64],   g_v  [2*1024*64];
__device__ bf16  g_qh [2*16*1024*64],g_ql [2*16*1024*64];
__device__ bf16  g_kh [2*1024*64],   g_kl [2*1024*64];
__device__ bf16  g_vh [2*1024*64],   g_vl [2*1024*64];
__device__ float g_nk [64], g_nv[64];
__device__ float g_o  [2*1024*1024];
__device__ bf16  g_oh [2*1024*1024], g_ol [2*1024*1024];
__device__ float g_y  [2*1024*1024];

// ---------------- cp.async helpers --------------------------------------------
__device__ __forceinline__ void cp_async16(void* smem, const void* gmem) {
    uint32_t s = (uint32_t)__cvta_generic_to_shared(smem);
    asm volatile("cp.async.cg.shared.global [%0], [%1], 16;\n" :: "r"(s), "l"(gmem));
}
__device__ __forceinline__ void cp_async4(void* smem, const void* gmem) {
    uint32_t s = (uint32_t)__cvta_generic_to_shared(smem);
    asm volatile("cp.async.ca.shared.global [%0], [%1], 4;\n" :: "r"(s), "l"(gmem));
}
#define CP_COMMIT() asm volatile("cp.async.commit_group;\n" ::)
#define CP_WAIT(N)  asm volatile("cp.async.wait_group %0;\n" :: "n"(N))

// ---------------- LayerNorm ----------------------------------------------------
__global__ __launch_bounds__(256) void ln_kernel(const float* __restrict__ x,
                                                 const float* __restrict__ g,
                                                 float* __restrict__ out) {
    const int row = blockIdx.x;
    const int tid = threadIdx.x;
    float4 a = ((const float4*)(x + (size_t)row * 1024))[tid];
    float s = a.x + a.y + a.z + a.w;
    float q = a.x * a.x + a.y * a.y + a.z * a.z + a.w * a.w;
    #pragma unroll
    for (int o = 16; o > 0; o >>= 1) {
        s += __shfl_xor_sync(0xffffffffu, s, o);
        q += __shfl_xor_sync(0xffffffffu, q, o);
    }
    __shared__ float ss[8], qq[8];
    if ((tid & 31) == 0) { ss[tid >> 5] = s; qq[tid >> 5] = q; }
    __syncthreads();
    if (tid < 32) {
        float s2 = (tid < 8) ? ss[tid] : 0.f;
        float q2 = (tid < 8) ? qq[tid] : 0.f;
        #pragma unroll
        for (int o = 4; o > 0; o >>= 1) {
            s2 += __shfl_xor_sync(0xffffffffu, s2, o);
            q2 += __shfl_xor_sync(0xffffffffu, q2, o);
        }
        if (tid == 0) { ss[0] = s2; qq[0] = q2; }
    }
    __syncthreads();
    const float mean = ss[0] * (1.f / 1024.f);
    const float var  = qq[0] * (1.f / 1024.f) - mean * mean;
    const float rstd = rsqrtf(var + 1e-5f);
    float4 gv = ((const float4*)g)[tid];
    float4 o4;
    o4.x = (a.x - mean) * rstd * gv.x;
    o4.y = (a.y - mean) * rstd * gv.y;
    o4.z = (a.z - mean) * rstd * gv.z;
    o4.w = (a.w - mean) * rstd * gv.w;
    ((float4*)(out + (size_t)row * 1024))[tid] = o4;
}

// ---------------- split fp32 -> bf16 hi/lo ------------------------------------
__global__ __launch_bounds__(256) void split_kernel(const float* __restrict__ src,
                                                    bf16* __restrict__ hi,
                                                    bf16* __restrict__ lo, int n4) {
    int i = blockIdx.x * 256 + threadIdx.x;
    if (i >= n4) return;
    float4 v = ((const float4*)src)[i];
    bf16 h0 = __float2bfloat16(v.x), h1 = __float2bfloat16(v.y);
    bf16 h2 = __float2bfloat16(v.z), h3 = __float2bfloat16(v.w);
    bf16 l0 = __float2bfloat16(v.x - __bfloat162float(h0));
    bf16 l1 = __float2bfloat16(v.y - __bfloat162float(h1));
    bf16 l2 = __float2bfloat16(v.z - __bfloat162float(h2));
    bf16 l3 = __float2bfloat16(v.w - __bfloat162float(h3));
    __nv_bfloat162* hp = (__nv_bfloat162*)(hi + 4 * (size_t)i);
    __nv_bfloat162* lp = (__nv_bfloat162*)(lo + 4 * (size_t)i);
    hp[0] = __halves2bfloat162(h0, h1); hp[1] = __halves2bfloat162(h2, h3);
    lp[0] = __halves2bfloat162(l0, l1); lp[1] = __halves2bfloat162(l2, l3);
}

// ---------------- bf16x3 GEMM, cp.async double-buffered ------------------------
// MODE 0: qkv  (A = xn split [2048x1024], B = combined w split [1152x1024])
// MODE 1: out  (A = o split [2048x1024],  B = wout split [1024x1024])
#define GLDA 40   // bf16 smem stride for 32-wide k tiles

template<int MODE>
__global__ __launch_bounds__(256, 2) void gemm_kernel() {
    extern __shared__ char smraw[];
    bf16* Ah = (bf16*)smraw;              // 2 stages * 128*40
    bf16* Al = Ah + 2 * 128 * GLDA;
    bf16* Bh = Al + 2 * 128 * GLDA;       // 2 stages * 64*40
    bf16* Bl = Bh + 2 * 64 * GLDA;

    const int nbase = blockIdx.x * 64;
    const int m0    = blockIdx.y * 128;
    const bf16 *gAh, *gAl, *gBh, *gBl;
    if (MODE == 0) {
        gAh = g_xnh; gAl = g_xnl;
        gBh = g_wh + (size_t)nbase * 1024; gBl = g_wl + (size_t)nbase * 1024;
    } else {
        gAh = g_oh; gAl = g_ol;
        gBh = g_woh + (size_t)nbase * 1024; gBl = g_wol + (size_t)nbase * 1024;
    }
    const int tid = threadIdx.x;
    const int warp = tid >> 5;
    const int wr = warp >> 1, wc = warp & 1;

    wmma::fragment<wmma::accumulator, 16, 16, 16, float> c[2][2];
    #pragma unroll
    for (int i = 0; i < 2; i++)
        #pragma unroll
        for (int j = 0; j < 2; j++) wmma::fill_fragment(c[i][j], 0.f);

    auto load_stage = [&](int s, int k0) {
        bf16* ah = Ah + s * 128 * GLDA; bf16* al = Al + s * 128 * GLDA;
        bf16* bh = Bh + s * 64  * GLDA; bf16* bl = Bl + s * 64  * GLDA;
        #pragma unroll
        for (int idx = tid; idx < 512; idx += 256) {     // A: 128 rows x 4 chunks
            int r = idx >> 2, c8 = idx & 3;
            cp_async16(ah + r * GLDA + c8 * 8, gAh + (size_t)(m0 + r) * 1024 + k0 + c8 * 8);
            cp_async16(al + r * GLDA + c8 * 8, gAl + (size_t)(m0 + r) * 1024 + k0 + c8 * 8);
        }
        {                                                // B: 64 rows x 4 chunks
            int r = tid >> 2, c8 = tid & 3;
            if (tid < 256) {
                cp_async16(bh + r * GLDA + c8 * 8, gBh + (size_t)r * 1024 + k0 + c8 * 8);
                cp_async16(bl + r * GLDA + c8 * 8, gBl + (size_t)r * 1024 + k0 + c8 * 8);
            }
        }
    };

    load_stage(0, 0);
    CP_COMMIT();

    for (int i = 0; i < 32; i++) {
        if (i < 31) load_stage((i + 1) & 1, (i + 1) * 32);
        CP_COMMIT();
        CP_WAIT(1);
        __syncthreads();
        const int s = i & 1;
        bf16* ahp = Ah + s * 128 * GLDA; bf16* alp = Al + s * 128 * GLDA;
        bf16* bhp = Bh + s * 64  * GLDA; bf16* blp = Bl + s * 64  * GLDA;
        #pragma unroll
        for (int kk = 0; kk < 2; kk++) {
            wmma::fragment<wmma::matrix_a, 16, 16, 16, bf16, wmma::row_major> ah[2], al[2];
            wmma::fragment<wmma::matrix_b, 16, 16, 16, bf16, wmma::col_major> bh[2], bl[2];
            #pragma unroll
            for (int t = 0; t < 2; t++) {
                wmma::load_matrix_sync(ah[t], ahp + (wr * 32 + t * 16) * GLDA + kk * 16, GLDA);
                wmma::load_matrix_sync(al[t], alp + (wr * 32 + t * 16) * GLDA + kk * 16, GLDA);
                wmma::load_matrix_sync(bh[t], bhp + (wc * 32 + t * 16) * GLDA + kk * 16, GLDA);
                wmma::load_matrix_sync(bl[t], blp + (wc * 32 + t * 16) * GLDA + kk * 16, GLDA);
            }
            #pragma unroll
            for (int t = 0; t < 2; t++)
                #pragma unroll
                for (int j = 0; j < 2; j++) {
                    wmma::mma_sync(c[t][j], ah[t], bh[j], c[t][j]);
                    wmma::mma_sync(c[t][j], ah[t], bl[j], c[t][j]);
                    wmma::mma_sync(c[t][j], al[t], bh[j], c[t][j]);
                }
        }
        __syncthreads();
    }

    if (MODE == 0) {
        const int b  = m0 >> 10;
        const int i0 = m0 & 1023;
        float* dest;
        if (nbase < 1024) {
            const int h = nbase >> 6;
            dest = g_q + ((size_t)(b * 16 + h) * 1024 + i0) * 64;
        } else if (nbase == 1024) {
            dest = g_k + ((size_t)b * 1024 + i0) * 64;
        } else {
            dest = g_v + ((size_t)b * 1024 + i0) * 64;
        }
        #pragma unroll
        for (int i = 0; i < 2; i++)
            #pragma unroll
            for (int j = 0; j < 2; j++)
                wmma::store_matrix_sync(dest + (size_t)(wr * 32 + i * 16) * 64 + (wc * 32 + j * 16),
                                        c[i][j], 64, wmma::mem_row_major);
    } else {
        #pragma unroll
        for (int i = 0; i < 2; i++)
            #pragma unroll
            for (int j = 0; j < 2; j++)
                wmma::store_matrix_sync(g_y + (size_t)(m0 + wr * 32 + i * 16) * 1024 + nbase + wc * 32 + j * 16,
                                        c[i][j], 1024, wmma::mem_row_major);
    }
}

// ---------------- l2norm -------------------------------------------------------
__global__ __launch_bounds__(256) void l2norm_kernel(const float* __restrict__ null_kv) {
    const int row  = blockIdx.x * 8 + (threadIdx.x >> 5);
    const int lane = threadIdx.x & 31;
    if (row > 34817) return;
    if (row == 34816) {
        float v0 = null_kv[lane], v1 = null_kv[lane + 32];
        float s = v0 * v0 + v1 * v1;
        #pragma unroll
        for (int o = 16; o > 0; o >>= 1) s += __shfl_xor_sync(0xffffffffu, s, o);
        float sc = 4.f / fmaxf(sqrtf(s), 1e-12f);
        g_nk[lane] = v0 * sc; g_nk[lane + 32] = v1 * sc;
        return;
    }
    if (row == 34817) {
        g_nv[lane] = null_kv[64 + lane];
        g_nv[lane + 32] = null_kv[96 + lane];
        return;
    }
    float* p = (row < 32768) ? (g_q + (size_t)row * 64)
                             : (g_k + (size_t)(row - 32768) * 64);
    float v0 = p[lane], v1 = p[lane + 32];
    float s = v0 * v0 + v1 * v1;
    #pragma unroll
    for (int o = 16; o > 0; o >>= 1) s += __shfl_xor_sync(0xffffffffu, s, o);
    float sc = 4.f / fmaxf(sqrtf(s), 1e-12f);
    p[lane] = v0 * sc; p[lane + 32] = v1 * sc;
}

// ---------------- attention (bf16x3, cp.async pipelined) -----------------------
#define SB   72     // bf16 tile stride
#define LDS_ 68     // fp32 stride (S, bias)
#define ATTN_SMEM_BYTES (6*64*SB*2 + 2*64*LDS_*4 + 384*4)   // 91648

__global__ __launch_bounds__(256, 2) void attn_kernel(const float* __restrict__ bias) {
    extern __shared__ char smraw[];
    bf16*  PQh = (bf16*)smraw;          // Q (prologue) then P
    bf16*  PQl = PQh + 64 * SB;
    bf16*  Kh  = PQl + 64 * SB;
    bf16*  Kl  = Kh  + 64 * SB;
    bf16*  Vh  = Kl  + 64 * SB;
    bf16*  Vl  = Vh  + 64 * SB;
    float* Ss  = (float*)(Vl + 64 * SB);
    float* Bs  = Ss + 64 * LDS_;
    float* e0  = Bs + 64 * LDS_;
    float* den = e0 + 64;
    float* denp = den + 64;

    const int qt = blockIdx.x, bh = blockIdx.y;
    const int b = bh >> 4, h = bh & 15;
    const int i0 = qt * 64;
    const int tid = threadIdx.x;
    const int warp = tid >> 5;
    const int wr = warp >> 1, wc = warp & 1;

    const float* bias_p = bias + (size_t)bh * 1024 * 1025;
    const bf16* khb = g_kh + (size_t)b * 1024 * 64;
    const bf16* klb = g_kl + (size_t)b * 1024 * 64;
    const bf16* vhb = g_vh + (size_t)b * 1024 * 64;
    const bf16* vlb = g_vl + (size_t)b * 1024 * 64;
    const bf16* qhb = g_qh + ((size_t)(b * 16 + h) * 1024 + i0) * 64;
    const bf16* qlb = g_ql + ((size_t)(b * 16 + h) * 1024 + i0) * 64;

    // prologue: G1 = {Q, K0, V0},  G2 = {bias0}
    #pragma unroll
    for (int idx = tid; idx < 512; idx += 256) {
        int r = idx >> 3, c8 = idx & 7;
        cp_async16(PQh + r * SB + c8 * 8, qhb + (size_t)r * 64 + c8 * 8);
        cp_async16(PQl + r * SB + c8 * 8, qlb + (size_t)r * 64 + c8 * 8);
        cp_async16(Kh  + r * SB + c8 * 8, khb + (size_t)r * 64 + c8 * 8);
        cp_async16(Kl  + r * SB + c8 * 8, klb + (size_t)r * 64 + c8 * 8);
        cp_async16(Vh  + r * SB + c8 * 8, vhb + (size_t)r * 64 + c8 * 8);
        cp_async16(Vl  + r * SB + c8 * 8, vlb + (size_t)r * 64 + c8 * 8);
    }
    CP_COMMIT();
    #pragma unroll 4
    for (int idx = tid; idx < 4096; idx += 256) {
        int r = idx >> 6, c = idx & 63;
        cp_async4(Bs + r * LDS_ + c, bias_p + (size_t)(i0 + r) * 1025 + 1 + c);
    }
    CP_COMMIT();
    CP_WAIT(1);
    __syncthreads();

    // Q fragments -> registers (held for whole kernel)
    wmma::fragment<wmma::matrix_a, 16, 16, 16, bf16, wmma::row_major> qfh[4], qfl[4];
    #pragma unroll
    for (int kk = 0; kk < 4; kk++) {
        wmma::load_matrix_sync(qfh[kk], PQh + wr * 16 * SB + kk * 16, SB);
        wmma::load_matrix_sync(qfl[kk], PQl + wr * 16 * SB + kk * 16, SB);
    }

    // null-key column
    if (tid < 64) {
        float s = 0.f;
        #pragma unroll 8
        for (int d = 0; d < 64; d++)
            s += (__bfloat162float(PQh[tid * SB + d]) + __bfloat162float(PQl[tid * SB + d])) * g_nk[d];
        float e = __expf(s + bias_p[(size_t)(i0 + tid) * 1025]);
        e0[tid] = e;
        den[tid] = e;
    }
    __syncthreads();   // Q smem consumed; PQ may now become P

    wmma::fragment<wmma::accumulator, 16, 16, 16, float> of[2];
    wmma::fill_fragment(of[0], 0.f);
    wmma::fill_fragment(of[1], 0.f);

    for (int kt = 0; kt < 16; kt++) {
        // ---- S = Q K^T (bf16x3) ----
        wmma::fragment<wmma::accumulator, 16, 16, 16, float> sf[2];
        wmma::fill_fragment(sf[0], 0.f);
        wmma::fill_fragment(sf[1], 0.f);
        #pragma unroll
        for (int kk = 0; kk < 4; kk++) {
            #pragma unroll
            for (int j = 0; j < 2; j++) {
                wmma::fragment<wmma::matrix_b, 16, 16, 16, bf16, wmma::col_major> kbh, kbl;
                wmma::load_matrix_sync(kbh, Kh + (wc * 32 + j * 16) * SB + kk * 16, SB);
                wmma::load_matrix_sync(kbl, Kl + (wc * 32 + j * 16) * SB + kk * 16, SB);
                wmma::mma_sync(sf[j], qfh[kk], kbh, sf[j]);
                wmma::mma_sync(sf[j], qfh[kk], kbl, sf[j]);
                wmma::mma_sync(sf[j], qfl[kk], kbh, sf[j]);
            }
        }
        #pragma unroll
        for (int j = 0; j < 2; j++)
            wmma::store_matrix_sync(Ss + wr * 16 * LDS_ + wc * 32 + j * 16, sf[j], LDS_,
                                    wmma::mem_row_major);
        __syncthreads();                              // K consumed, S ready

        // issue K(kt+1)
        if (kt < 15) {
            int j0n = (kt + 1) * 64;
            #pragma unroll
            for (int idx = tid; idx < 512; idx += 256) {
                int r = idx >> 3, c8 = idx & 7;
                cp_async16(Kh + r * SB + c8 * 8, khb + (size_t)(j0n + r) * 64 + c8 * 8);
                cp_async16(Kl + r * SB + c8 * 8, klb + (size_t)(j0n + r) * 64 + c8 * 8);
            }
        }
        CP_COMMIT();
        CP_WAIT(1);                                   // drains bias(kt) (+V(kt) from prev iter)
        __syncthreads();

        // ---- P = exp(S + bias), split to bf16 hi/lo ----
        {
            const int r = tid >> 2, cb = (tid & 3) * 16;
            float local = 0.f;
            #pragma unroll
            for (int c = 0; c < 16; c++) {
                float p = __expf(Ss[r * LDS_ + cb + c] + Bs[r * LDS_ + cb + c]);
                local += p;
                bf16 ph = __float2bfloat16(p);
                PQh[r * SB + cb + c] = ph;
                PQl[r * SB + cb + c] = __float2bfloat16(p - __bfloat162float(ph));
            }
            denp[tid] = local;
        }
        __syncthreads();
        if (tid < 64)
            den[tid] += denp[4 * tid] + denp[4 * tid + 1] + denp[4 * tid + 2] + denp[4 * tid + 3];

        // ---- O += P V (bf16x3) ----
        #pragma unroll
        for (int kk = 0; kk < 4; kk++) {
            wmma::fragment<wmma::matrix_a, 16, 16, 16, bf16, wmma::row_major> pfh, pfl;
            wmma::load_matrix_sync(pfh, PQh + wr * 16 * SB + kk * 16, SB);
            wmma::load_matrix_sync(pfl, PQl + wr * 16 * SB + kk * 16, SB);
            #pragma unroll
            for (int j = 0; j < 2; j++) {
                wmma::fragment<wmma::matrix_b, 16, 16, 16, bf16, wmma::row_major> vbh, vbl;
                wmma::load_matrix_sync(vbh, Vh + kk * 16 * SB + wc * 32 + j * 16, SB);
                wmma::load_matrix_sync(vbl, Vl + kk * 16 * SB + wc * 32 + j * 16, SB);
                wmma::mma_sync(of[j], pfh, vbh, of[j]);
                wmma::mma_sync(of[j], pfh, vbl, of[j]);
                wmma::mma_sync(of[j], pfl, vbh, of[j]);
            }
        }
        __syncthreads();                              // V and P consumed

        // issue V(kt+1) and bias(kt+1)
        if (kt < 15) {
            int j0n = (kt + 1) * 64;
            #pragma unroll
            for (int idx = tid; idx < 512; idx += 256) {
                int r = idx >> 3, c8 = idx & 7;
                cp_async16(Vh + r * SB + c8 * 8, vhb + (size_t)(j0n + r) * 64 + c8 * 8);
                cp_async16(Vl + r * SB + c8 * 8, vlb + (size_t)(j0n + r) * 64 + c8 * 8);
            }
        }
        CP_COMMIT();
        if (kt < 15) {
            int j0n = (kt + 1) * 64;
            #pragma unroll 4
            for (int idx = tid; idx < 4096; idx += 256) {
                int r = idx >> 6, c = idx & 63;
                cp_async4(Bs + r * LDS_ + c, bias_p + (size_t)(i0 + r) * 1025 + 1 + j0n + c);
            }
        }
        CP_COMMIT();
        CP_WAIT(2);                                   // drains K(kt+1); leaves V,B in flight
        __syncthreads();
    }
    CP_WAIT(0);

    // epilogue
    #pragma unroll
    for (int j = 0; j < 2; j++)
        wmma::store_matrix_sync(Ss + wr * 16 * LDS_ + wc * 32 + j * 16, of[j], LDS_,
                                wmma::mem_row_major);
    __syncthreads();
    {
        const int r = tid >> 2, cb = (tid & 3) * 16;
        const float invd = 1.f / den[r];
        const float e = e0[r];
        float* op = g_o + ((size_t)(b * 1024 + i0 + r)) * 1024 + h * 64 + cb;
        #pragma unroll
        for (int c = 0; c < 16; c++)
            op[c] = (Ss[r * LDS_ + cb + c] + e * g_nv[cb + c]) * invd;
    }
}

// ---------------- launch -------------------------------------------------------
extern "C" void kernel_launch(void* const* d_in, const int* in_sizes, int n_in,
                              void* d_out, int out_size) {
    const float* x       = (const float*)d_in[0];
    const float* bias    = (const float*)d_in[1];
    const float* g_in    = (const float*)d_in[2];
    const float* w_q     = (const float*)d_in[3];
    const float* w_kv    = (const float*)d_in[4];
    const float* null_kv = (const float*)d_in[5];
    const float* w_out   = (const float*)d_in[6];
    const float* g_out   = (const float*)d_in[7];
    float* out = (float*)d_out;

    float *xn_p, *q_p, *k_p, *v_p, *o_p, *y_p;
    bf16 *xnh_p, *xnl_p, *wh_p, *wl_p, *woh_p, *wol_p;
    bf16 *qh_p, *ql_p, *kh_p, *kl_p, *vh_p, *vl_p, *oh_p, *ol_p;
    cudaGetSymbolAddress((void**)&xn_p, g_xn);
    cudaGetSymbolAddress((void**)&q_p,  g_q);
    cudaGetSymbolAddress((void**)&k_p,  g_k);
    cudaGetSymbolAddress((void**)&v_p,  g_v);
    cudaGetSymbolAddress((void**)&o_p,  g_o);
    cudaGetSymbolAddress((void**)&y_p,  g_y);
    cudaGetSymbolAddress((void**)&xnh_p, g_xnh);
    cudaGetSymbolAddress((void**)&xnl_p, g_xnl);
    cudaGetSymbolAddress((void**)&wh_p,  g_wh);
    cudaGetSymbolAddress((void**)&wl_p,  g_wl);
    cudaGetSymbolAddress((void**)&woh_p, g_woh);
    cudaGetSymbolAddress((void**)&wol_p, g_wol);
    cudaGetSymbolAddress((void**)&qh_p,  g_qh);
    cudaGetSymbolAddress((void**)&ql_p,  g_ql);
    cudaGetSymbolAddress((void**)&kh_p,  g_kh);
    cudaGetSymbolAddress((void**)&kl_p,  g_kl);
    cudaGetSymbolAddress((void**)&vh_p,  g_vh);
    cudaGetSymbolAddress((void**)&vl_p,  g_vl);
    cudaGetSymbolAddress((void**)&oh_p,  g_oh);
    cudaGetSymbolAddress((void**)&ol_p,  g_ol);

    const int GEMM_SMEM = (2 * 128 * GLDA + 2 * 128 * GLDA + 2 * 64 * GLDA + 2 * 64 * GLDA) * 2; // 61440
    cudaFuncSetAttribute(gemm_kernel<0>, cudaFuncAttributeMaxDynamicSharedMemorySize, GEMM_SMEM);
    cudaFuncSetAttribute(gemm_kernel<1>, cudaFuncAttributeMaxDynamicSharedMemorySize, GEMM_SMEM);
    cudaFuncSetAttribute(attn_kernel, cudaFuncAttributeMaxDynamicSharedMemorySize, ATTN_SMEM_BYTES);

    // 1. LN(x)
    ln_kernel<<<2048, 256>>>(x, g_in, xn_p);
    // 2. splits of xn and weights
    split_kernel<<<2048, 256>>>(xn_p, xnh_p, xnl_p, 524288);
    split_kernel<<<1024, 256>>>(w_q,  wh_p, wl_p, 262144);
    split_kernel<<<128,  256>>>(w_kv, wh_p + 1024 * 1024, wl_p + 1024 * 1024, 32768);
    split_kernel<<<1024, 256>>>(w_out, woh_p, wol_p, 262144);
    // 3. fused QKV GEMM (bf16x3)
    gemm_kernel<0><<<dim3(18, 16), 256, GEMM_SMEM>>>();
    // 4. l2norm q/k rows + null kv prep
    l2norm_kernel<<<(32768 + 2048 + 2 + 7) / 8, 256>>>(null_kv);
    // 5. split q/k/v
    split_kernel<<<2048, 256>>>(q_p, qh_p, ql_p, 524288);
    split_kernel<<<128,  256>>>(k_p, kh_p, kl_p, 32768);
    split_kernel<<<128,  256>>>(v_p, vh_p, vl_p, 32768);
    // 6. attention
    attn_kernel<<<dim3(16, 32), 256, ATTN_SMEM_BYTES>>>(bias);
    // 7. split o, out projection
    split_kernel<<<2048, 256>>>(o_p, oh_p, ol_p, 524288);
    gemm_kernel<1><<<dim3(16, 16), 256, GEMM_SMEM>>>();
    // 8. final LN
    ln_kernel<<<2048, 256>>>(y_p, g_out, out);
}